// round 5
// baseline (speedup 1.0000x reference)
#include <cuda_runtime.h>
#include <math.h>

#define MAXB 16
#define MAXA 262144
#define PRE  2000
#define PREP 2048
#define POST 1000
#define SELCAP 4096
#define NWORD 32           // ceil(PRE/64)

// ---------------- scratch (device globals; no allocation) ----------------
__device__ float4              g_boxes4[(size_t)MAXB * MAXA];      // clipped boxes
__device__ unsigned            g_keys[(size_t)MAXB * MAXA];        // monotonic score keys
__device__ unsigned            g_hist[MAXB * 2048];
__device__ unsigned            g_prefix[MAXB];
__device__ unsigned            g_need[MAXB];
__device__ unsigned            g_thresh[MAXB];
__device__ unsigned            g_selcnt[MAXB];
__device__ unsigned long long  g_sel[MAXB * SELCAP];
__device__ float4              g_nmsBoxes4[MAXB * PREP];
__device__ float               g_topScore[MAXB * PREP];
__device__ unsigned long long  g_mask[(size_t)MAXB * PREP * NWORD];
__device__ unsigned long long  g_removed[MAXB * NWORD];

__device__ __forceinline__ unsigned mono(float f) {
    unsigned u = __float_as_uint(f);
    return (u & 0x80000000u) ? ~u : (u | 0x80000000u);
}
__device__ __forceinline__ float imono(unsigned m) {
    unsigned u = (m & 0x80000000u) ? (m ^ 0x80000000u) : ~m;
    return __uint_as_float(u);
}

// ---------------- 1. decode + clip + validity + keys ----------------
__global__ void kDecode(const float* __restrict__ anc, const float* __restrict__ del,
                        const float* __restrict__ sco, int A, int n) {
    int idx = blockIdx.x * blockDim.x + threadIdx.x;
    if (idx >= n) return;
    int a = idx % A;
    const float* ap = anc + (size_t)a * 4;
    float a0 = ap[0], a1 = ap[1], a2 = ap[2], a3 = ap[3];
    float aw = __fsub_rn(a2, a0), ah = __fsub_rn(a3, a1);
    float ax = __fadd_rn(a0, __fmul_rn(0.5f, aw));
    float ay = __fadd_rn(a1, __fmul_rn(0.5f, ah));
    const float* dp = del + (size_t)idx * 4;
    float dx = dp[0], dy = dp[1];
    float dw = fminf(dp[2], 4.0f), dh = fminf(dp[3], 4.0f);
    float px = __fadd_rn(__fmul_rn(dx, aw), ax);
    float py = __fadd_rn(__fmul_rn(dy, ah), ay);
    float pw = __fmul_rn(expf(dw), aw);
    float ph = __fmul_rn(expf(dh), ah);
    float x1 = __fsub_rn(px, __fmul_rn(0.5f, pw));
    float y1 = __fsub_rn(py, __fmul_rn(0.5f, ph));
    float x2 = __fadd_rn(px, __fmul_rn(0.5f, pw));
    float y2 = __fadd_rn(py, __fmul_rn(0.5f, ph));
    x1 = fminf(fmaxf(x1, 0.0f), 1024.0f);
    y1 = fminf(fmaxf(y1, 0.0f), 1024.0f);
    x2 = fminf(fmaxf(x2, 0.0f), 1024.0f);
    y2 = fminf(fmaxf(y2, 0.0f), 1024.0f);
    bool valid = (__fsub_rn(x2, x1) >= 16.0f) && (__fsub_rn(y2, y1) >= 16.0f);
    float s = sco[idx];
    float ms = valid ? s : __int_as_float(0xFF800000);  // -inf
    g_keys[idx] = mono(ms);
    g_boxes4[idx] = make_float4(x1, y1, x2, y2);
}

// ---------------- 2a. radix-histogram threshold selection ----------------
__global__ void kZeroHist(int n) {
    int i = blockIdx.x * blockDim.x + threadIdx.x;
    if (i < n) g_hist[i] = 0;
}

__global__ void kHist(int level, int A) {
    __shared__ unsigned sh[2048];
    int b = blockIdx.y;
    for (int i = threadIdx.x; i < 2048; i += blockDim.x) sh[i] = 0;
    __syncthreads();
    unsigned pfx = g_prefix[b];
    const unsigned* keys = g_keys + (size_t)b * A;
    for (int a = blockIdx.x * blockDim.x + threadIdx.x; a < A; a += gridDim.x * blockDim.x) {
        unsigned k = keys[a];
        if (level == 0) atomicAdd(&sh[k >> 21], 1u);
        else if (level == 1) { if ((k >> 21) == pfx) atomicAdd(&sh[(k >> 10) & 0x7FFu], 1u); }
        else               { if ((k >> 10) == pfx) atomicAdd(&sh[k & 0x3FFu], 1u); }
    }
    __syncthreads();
    for (int i = threadIdx.x; i < 2048; i += blockDim.x)
        if (sh[i]) atomicAdd(&g_hist[b * 2048 + i], sh[i]);
}

__global__ void kSelect(int level) {
    int b = blockIdx.x;
    if (threadIdx.x != 0) return;
    unsigned need = (level == 0) ? (unsigned)PRE : g_need[b];
    const unsigned* h = &g_hist[b * 2048];
    int nb = (level == 2) ? 1024 : 2048;
    unsigned cum = 0;
    int bin = nb - 1;
    for (; bin >= 0; --bin) {
        unsigned c = h[bin];
        if (cum + c >= need) break;
        cum += c;
    }
    if (bin < 0) bin = 0;
    g_need[b] = need - cum;
    if (level == 0)      g_prefix[b] = (unsigned)bin;
    else if (level == 1) g_prefix[b] = (g_prefix[b] << 11) | (unsigned)bin;
    else { g_thresh[b] = (g_prefix[b] << 10) | (unsigned)bin; g_selcnt[b] = 0; }
}

// ---------------- 2b. collect key >= T ----------------
__global__ void kCollect(int A) {
    int b = blockIdx.y;
    unsigned T = g_thresh[b];
    const unsigned* keys = g_keys + (size_t)b * A;
    for (int a = blockIdx.x * blockDim.x + threadIdx.x; a < A; a += gridDim.x * blockDim.x) {
        unsigned k = keys[a];
        if (k >= T) {
            unsigned p = atomicAdd(&g_selcnt[b], 1u);
            if (p < SELCAP)
                g_sel[b * SELCAP + p] =
                    ((unsigned long long)k << 32) | (unsigned)(~(unsigned)a);
        }
    }
}

// ---------------- 2c. bitonic sort (score desc, idx asc), gather top-2000 ----------------
__global__ void kSort(int A) {
    __shared__ unsigned long long s[SELCAP];
    int b = blockIdx.x, t = threadIdx.x;
    unsigned cnt = g_selcnt[b];
    if (cnt > SELCAP) cnt = SELCAP;
    for (int i = t; i < SELCAP; i += blockDim.x)
        s[i] = (i < (int)cnt) ? g_sel[b * SELCAP + i] : 0ull;
    __syncthreads();
    for (int k = 2; k <= SELCAP; k <<= 1) {
        for (int j = k >> 1; j > 0; j >>= 1) {
            for (int i = t; i < SELCAP; i += blockDim.x) {
                int l = i ^ j;
                if (l > i) {
                    bool dir = ((i & k) == 0);   // descending block
                    unsigned long long x = s[i], y = s[l];
                    if ((x < y) == dir) { s[i] = y; s[l] = x; }
                }
            }
            __syncthreads();
        }
    }
    for (int i = t; i < PRE; i += blockDim.x) {
        unsigned long long v = s[i];
        unsigned key = (unsigned)(v >> 32);
        unsigned a = ~(unsigned)(v & 0xFFFFFFFFull);
        g_topScore[b * PREP + i] = imono(key);
        g_nmsBoxes4[b * PREP + i] = g_boxes4[(size_t)b * A + a];
    }
}

// ---------------- 3. NMS suppression bitmask ----------------
__global__ void kMask() {
    int b = blockIdx.z;
    int ib = blockIdx.x, jb = blockIdx.y;
    __shared__ float4 cb[64];
    int j0 = jb * 64;
    int t = threadIdx.x;
    if (j0 + t < PRE) cb[t] = g_nmsBoxes4[b * PREP + j0 + t];
    __syncthreads();
    int i = ib * 64 + t;
    if (i >= PRE) return;
    float4 mb = g_nmsBoxes4[b * PREP + i];
    float areaI = __fmul_rn(__fsub_rn(mb.z, mb.x), __fsub_rn(mb.w, mb.y));
    unsigned long long m = 0;
    int jmax = min(64, PRE - j0);
    if (j0 + jmax - 1 > i) {
        for (int jj = 0; jj < jmax; ++jj) {
            int j = j0 + jj;
            if (j <= i) continue;
            float4 ob = cb[jj];
            float areaJ = __fmul_rn(__fsub_rn(ob.z, ob.x), __fsub_rn(ob.w, ob.y));
            float ltx = fmaxf(mb.x, ob.x), lty = fmaxf(mb.y, ob.y);
            float rbx = fminf(mb.z, ob.z), rby = fminf(mb.w, ob.w);
            float w = fmaxf(__fsub_rn(rbx, ltx), 0.0f);
            float h = fmaxf(__fsub_rn(rby, lty), 0.0f);
            float inter = __fmul_rn(w, h);
            float den = __fadd_rn(__fsub_rn(__fadd_rn(areaI, areaJ), inter), 1e-6f);
            if (__fdiv_rn(inter, den) > 0.7f) m |= (1ull << jj);
        }
    }
    g_mask[((size_t)b * PREP + i) * NWORD + jb] = m;
}

// ---------------- 4. greedy sequential scan (1 warp / batch) ----------------
__global__ void kScan() {
    int b = blockIdx.x, t = threadIdx.x;   // 32 threads
    __shared__ unsigned long long rem[NWORD];
    rem[t] = 0;
    __syncwarp();
    const unsigned long long* mrow = &g_mask[(size_t)b * PREP * NWORD];
    unsigned long long nxt = mrow[t];
    for (int i = 0; i < PRE; ++i) {
        unsigned long long cur = nxt;
        if (i + 1 < PRE) nxt = mrow[(size_t)(i + 1) * NWORD + t];
        bool alive = !((rem[i >> 6] >> (i & 63)) & 1ull);
        __syncwarp();
        if (alive) rem[t] |= cur;
        __syncwarp();
    }
    g_removed[b * NWORD + t] = rem[t];
}

// ---------------- 5. rank kept entries, write output ----------------
__global__ void kOut(float* __restrict__ out) {
    int b = blockIdx.x, t = threadIdx.x;
    __shared__ int rank[PRE];
    __shared__ int totalS;
    if (t == 0) {
        int r = 0;
        for (int i = 0; i < PRE; ++i) {
            unsigned long long w = g_removed[b * NWORD + (i >> 6)];
            bool keep = !((w >> (i & 63)) & 1ull);
            rank[i] = keep ? r++ : -1;
        }
        totalS = r;
    }
    __syncthreads();
    float* ob = out + (size_t)b * POST * 5;
    for (int i = t; i < PRE; i += blockDim.x) {
        int r = rank[i];
        if (r >= 0 && r < POST) {
            float s = g_topScore[b * PREP + i];
            float4 bx = g_nmsBoxes4[b * PREP + i];
            if (isfinite(s)) {
                ob[r * 5 + 0] = bx.x; ob[r * 5 + 1] = bx.y;
                ob[r * 5 + 2] = bx.z; ob[r * 5 + 3] = bx.w;
                ob[r * 5 + 4] = s;
            } else {
                ob[r * 5 + 0] = 0.f; ob[r * 5 + 1] = 0.f;
                ob[r * 5 + 2] = 0.f; ob[r * 5 + 3] = 0.f;
                ob[r * 5 + 4] = 0.f;
            }
        }
    }
    int total = totalS;
    for (int r = total + t; r < POST; r += blockDim.x) {
        ob[r * 5 + 0] = 0.f; ob[r * 5 + 1] = 0.f;
        ob[r * 5 + 2] = 0.f; ob[r * 5 + 3] = 0.f;
        ob[r * 5 + 4] = 0.f;
    }
}

// ---------------- launch ----------------
extern "C" void kernel_launch(void* const* d_in, const int* in_sizes, int n_in,
                              void* d_out, int out_size) {
    const float* anchors = (const float*)d_in[0];
    const float* deltas  = (const float*)d_in[1];
    const float* scores  = (const float*)d_in[2];
    float* out = (float*)d_out;
    int A = in_sizes[0] / 4;
    int B = in_sizes[2] / A;
    int n = A * B;

    kDecode<<<(n + 255) / 256, 256>>>(anchors, deltas, scores, A, n);

    for (int lvl = 0; lvl < 3; ++lvl) {
        int hn = B * 2048;
        kZeroHist<<<(hn + 255) / 256, 256>>>(hn);
        kHist<<<dim3(64, B), 256>>>(lvl, A);
        kSelect<<<B, 32>>>(lvl);
    }
    kCollect<<<dim3(128, B), 256>>>(A);
    kSort<<<B, 1024>>>(A);

    dim3 mg((PRE + 63) / 64, (PRE + 63) / 64, B);
    kMask<<<mg, 64>>>();
    kScan<<<B, 32>>>();
    kOut<<<B, 256>>>(out);
}

// round 6
// speedup vs baseline: 1.4249x; 1.4249x over previous
#include <cuda_runtime.h>
#include <math.h>

#define MAXB 16
#define PRE  2000
#define PREP 2048
#define POST 1000
#define SELCAP 4096
#define NWORD 32           // ceil(PRE/64)
#define NBIN 4096
#define SBIN 4055
#define SBIN_F 0.989990234375f   // 4055/4096 exactly

// ---------------- scratch (device globals; no allocation) ----------------
__device__ unsigned            g_selcnt[MAXB];
__device__ int                 g_fb[MAXB];
__device__ unsigned            g_thresh[MAXB];
__device__ unsigned            g_hist[MAXB * NBIN];
__device__ unsigned long long  g_sel[MAXB * SELCAP];
__device__ float4              g_nmsBoxes4[MAXB * PREP];
__device__ float               g_topScore[MAXB * PREP];
__device__ unsigned long long  g_mask[(size_t)MAXB * PREP * NWORD];
__device__ unsigned long long  g_removed[MAXB * NWORD];

__device__ __forceinline__ unsigned mono(float f) {
    unsigned u = __float_as_uint(f);
    return (u & 0x80000000u) ? ~u : (u | 0x80000000u);
}
__device__ __forceinline__ float imono(unsigned m) {
    unsigned u = (m & 0x80000000u) ? (m ^ 0x80000000u) : ~m;
    return __uint_as_float(u);
}

// Exact decode path — must match XLA op-for-op (separate mul/add roundings).
__device__ __forceinline__ float4 decodeBoxExact(float4 av, float4 dv) {
    float aw = __fsub_rn(av.z, av.x), ah = __fsub_rn(av.w, av.y);
    float ax = __fadd_rn(av.x, __fmul_rn(0.5f, aw));
    float ay = __fadd_rn(av.y, __fmul_rn(0.5f, ah));
    float dw = fminf(dv.z, 4.0f), dh = fminf(dv.w, 4.0f);
    float px = __fadd_rn(__fmul_rn(dv.x, aw), ax);
    float py = __fadd_rn(__fmul_rn(dv.y, ah), ay);
    float pw = __fmul_rn(expf(dw), aw);
    float ph = __fmul_rn(expf(dh), ah);
    float hx = __fmul_rn(0.5f, pw), hy = __fmul_rn(0.5f, ph);
    float x1 = __fsub_rn(px, hx), y1 = __fsub_rn(py, hy);
    float x2 = __fadd_rn(px, hx), y2 = __fadd_rn(py, hy);
    return make_float4(fminf(fmaxf(x1, 0.0f), 1024.0f),
                       fminf(fmaxf(y1, 0.0f), 1024.0f),
                       fminf(fmaxf(x2, 0.0f), 1024.0f),
                       fminf(fmaxf(y2, 0.0f), 1024.0f));
}
__device__ __forceinline__ bool validExact(float4 bx) {
    return (__fsub_rn(bx.z, bx.x) >= 16.0f) && (__fsub_rn(bx.w, bx.y) >= 16.0f);
}

// ---------------- 0. per-replay reset ----------------
__global__ void kInit(int nb) {
    int i = blockIdx.x * 256 + threadIdx.x;
    if (i < nb * NBIN) g_hist[i] = 0;
    if (i < nb)        g_selcnt[i] = 0;
}

// ---------------- 1. lazy decode + speculative candidate push ----------------
__global__ void kDecode(const float* __restrict__ anc, const float* __restrict__ del,
                        const float* __restrict__ sco, int A, int nb) {
    int a0 = blockIdx.x * 256 + threadIdx.x;
    bool inb = (a0 < A);
    int a = inb ? a0 : (A - 1);
    int lane = threadIdx.x & 31;

    float4 av = ((const float4*)anc)[a];
    float aw = __fsub_rn(av.z, av.x), ah = __fsub_rn(av.w, av.y);
    float ax = __fadd_rn(av.x, __fmul_rn(0.5f, aw));
    float ay = __fadd_rn(av.y, __fmul_rn(0.5f, ah));

    for (int b = 0; b < nb; ++b) {
        float s = sco[(size_t)b * A + a];
        bool cand = inb && (s >= SBIN_F);
        unsigned bal = __ballot_sync(0xFFFFFFFFu, cand);
        if (!bal) continue;

        // fast approximate box (all lanes; only cand lanes matter)
        float4 dv = ((const float4*)del)[(size_t)b * A + a];
        float dw = fminf(dv.z, 4.0f), dh = fminf(dv.w, 4.0f);
        float px = __fadd_rn(__fmul_rn(dv.x, aw), ax);
        float py = __fadd_rn(__fmul_rn(dv.y, ah), ay);
        float pw = __fmul_rn(__expf(dw), aw);
        float ph = __fmul_rn(__expf(dh), ah);
        float hx = __fmul_rn(0.5f, pw), hy = __fmul_rn(0.5f, ph);
        float cw = __fsub_rn(fminf(__fadd_rn(px, hx), 1024.0f),
                             fmaxf(__fsub_rn(px, hx), 0.0f));
        float ch = __fsub_rn(fminf(__fadd_rn(py, hy), 1024.0f),
                             fmaxf(__fsub_rn(py, hy), 0.0f));
        float mn = fminf(cw, ch);
        bool valid = false;
        if (cand) {
            if (mn >= 17.0f) valid = true;                 // sure-valid (margin 1px)
            else if (mn >= 15.0f) {                        // ambiguous -> exact
                valid = validExact(decodeBoxExact(av, dv));
            }                                              // mn < 15 -> sure-invalid
        }
        unsigned pb = __ballot_sync(0xFFFFFFFFu, valid);
        if (pb) {
            int leader = __ffs(pb) - 1;
            unsigned base = 0;
            if (lane == leader) base = atomicAdd(&g_selcnt[b], (unsigned)__popc(pb));
            base = __shfl_sync(0xFFFFFFFFu, base, leader);
            if (valid) {
                unsigned pos = base + (unsigned)__popc(pb & ((1u << lane) - 1u));
                if (pos < SELCAP) {
                    unsigned key = __float_as_uint(s) | 0x80000000u;   // s > 0 -> mono
                    g_sel[b * SELCAP + pos] =
                        ((unsigned long long)key << 32) | (unsigned)(~(unsigned)a);
                }
            }
        }
    }
}

// ---------------- 2. decide: speculation valid, or exact fallback? ----------------
__global__ void kDecide(int nb) {
    int b = threadIdx.x;
    if (b >= nb) return;
    unsigned c = g_selcnt[b];
    int fb = !(c >= PRE && c <= SELCAP);
    g_fb[b] = fb;
    if (fb) g_selcnt[b] = 0;          // collect will refill
}

// ---------------- fallback path (exact; early-exit when speculation holds) ----------
__global__ void kHistFB(const float* __restrict__ anc, const float* __restrict__ del,
                        const float* __restrict__ sco, int A) {
    int b = blockIdx.y;
    if (!g_fb[b]) return;
    for (int a = blockIdx.x * blockDim.x + threadIdx.x; a < A; a += gridDim.x * blockDim.x) {
        float4 av = ((const float4*)anc)[a];
        float4 dv = ((const float4*)del)[(size_t)b * A + a];
        if (!validExact(decodeBoxExact(av, dv))) continue;
        float s = sco[(size_t)b * A + a];
        int bin = (int)(__fmul_rn(s, 4096.0f));          // exact: power-of-two scale
        bin = max(0, min(NBIN - 1, bin));
        atomicAdd(&g_hist[b * NBIN + bin], 1u);
    }
}

__global__ void kSelFB() {
    int b = blockIdx.x;
    if (!g_fb[b] || threadIdx.x != 0) return;
    const unsigned* h = &g_hist[b * NBIN];
    unsigned cum = 0;
    int bin = NBIN - 1;
    for (; bin >= 0; --bin) {
        cum += h[bin];
        if (cum >= PRE) break;
    }
    if (bin < 0) bin = 0;
    g_thresh[b] = (unsigned)bin;
}

__global__ void kColFB(const float* __restrict__ anc, const float* __restrict__ del,
                       const float* __restrict__ sco, int A) {
    int b = blockIdx.y;
    if (!g_fb[b]) return;
    unsigned T = g_thresh[b];
    for (int a = blockIdx.x * blockDim.x + threadIdx.x; a < A; a += gridDim.x * blockDim.x) {
        float s = sco[(size_t)b * A + a];
        int bin = (int)(__fmul_rn(s, 4096.0f));
        bin = max(0, min(NBIN - 1, bin));
        if ((unsigned)bin < T) continue;
        float4 av = ((const float4*)anc)[a];
        float4 dv = ((const float4*)del)[(size_t)b * A + a];
        if (!validExact(decodeBoxExact(av, dv))) continue;
        unsigned p = atomicAdd(&g_selcnt[b], 1u);
        if (p < SELCAP)
            g_sel[b * SELCAP + p] =
                ((unsigned long long)mono(s) << 32) | (unsigned)(~(unsigned)a);
    }
}

// ---------------- 3. bitonic sort (score desc, idx asc) + re-decode winners --------
__global__ void kSort(const float* __restrict__ anc, const float* __restrict__ del, int A) {
    __shared__ unsigned long long s[SELCAP];
    int b = blockIdx.x, t = threadIdx.x;
    unsigned cnt = g_selcnt[b];
    if (cnt > SELCAP) cnt = SELCAP;
    for (int i = t; i < SELCAP; i += blockDim.x)
        s[i] = (i < (int)cnt) ? g_sel[b * SELCAP + i] : 0ull;
    __syncthreads();
    for (int k = 2; k <= SELCAP; k <<= 1) {
        for (int j = k >> 1; j > 0; j >>= 1) {
            for (int i = t; i < SELCAP; i += blockDim.x) {
                int l = i ^ j;
                if (l > i) {
                    bool dir = ((i & k) == 0);   // descending block
                    unsigned long long x = s[i], y = s[l];
                    if ((x < y) == dir) { s[i] = y; s[l] = x; }
                }
            }
            __syncthreads();
        }
    }
    for (int i = t; i < PRE; i += blockDim.x) {
        unsigned long long v = s[i];
        if (v) {
            unsigned key = (unsigned)(v >> 32);
            unsigned a = ~(unsigned)(v & 0xFFFFFFFFull);
            float4 av = ((const float4*)anc)[a];
            float4 dv = ((const float4*)del)[(size_t)b * A + a];
            g_nmsBoxes4[b * PREP + i] = decodeBoxExact(av, dv);
            g_topScore[b * PREP + i] = imono(key);
        } else {
            g_nmsBoxes4[b * PREP + i] = make_float4(0.f, 0.f, 0.f, 0.f);
            g_topScore[b * PREP + i] = __int_as_float(0xFF800000);   // -inf
        }
    }
}

// ---------------- 4. NMS suppression bitmask (div-free hot path) ----------------
__global__ void kMask() {
    int b = blockIdx.z, ib = blockIdx.x, jb = blockIdx.y;
    if (jb < ib) return;                    // uniform per block
    __shared__ float4 cb[64];
    __shared__ float  ca[64];
    int t = threadIdx.x;
    int j0 = jb * 64;
    int jmax = min(64, PRE - j0);
    if (t < jmax) {
        float4 o = g_nmsBoxes4[b * PREP + j0 + t];
        cb[t] = o;
        ca[t] = __fmul_rn(__fsub_rn(o.z, o.x), __fsub_rn(o.w, o.y));
    }
    __syncthreads();
    int i = ib * 64 + t;
    if (i >= PRE) return;
    float4 mb = g_nmsBoxes4[b * PREP + i];
    float areaI = __fmul_rn(__fsub_rn(mb.z, mb.x), __fsub_rn(mb.w, mb.y));
    unsigned long long m = 0, amb = 0;
    int jstart = (ib == jb) ? t + 1 : 0;
    #pragma unroll 4
    for (int jj = jstart; jj < jmax; ++jj) {
        float4 ob = cb[jj];
        float ltx = fmaxf(mb.x, ob.x), lty = fmaxf(mb.y, ob.y);
        float rbx = fminf(mb.z, ob.z), rby = fminf(mb.w, ob.w);
        float w = fmaxf(__fsub_rn(rbx, ltx), 0.0f);
        float h = fmaxf(__fsub_rn(rby, lty), 0.0f);
        float inter = __fmul_rn(w, h);
        float den = __fadd_rn(__fsub_rn(__fadd_rn(areaI, ca[jj]), inter), 1e-6f);
        float r = __fmaf_rn(-0.7f, den, inter);      // sign of inter - 0.7*den
        float eps = __fmul_rn(den, 2e-6f);
        unsigned long long bit = 1ull << jj;
        if (r > eps) m |= bit;                       // sure-suppress
        else if (r >= -eps) amb |= bit;              // ambiguous (rare)
    }
    if (amb) {                                       // exact div fixup, decision-identical
        unsigned long long aa = amb;
        while (aa) {
            int jj = __ffsll((long long)aa) - 1;
            aa &= aa - 1;
            float4 ob = cb[jj];
            float ltx = fmaxf(mb.x, ob.x), lty = fmaxf(mb.y, ob.y);
            float rbx = fminf(mb.z, ob.z), rby = fminf(mb.w, ob.w);
            float w = fmaxf(__fsub_rn(rbx, ltx), 0.0f);
            float h = fmaxf(__fsub_rn(rby, lty), 0.0f);
            float inter = __fmul_rn(w, h);
            float den = __fadd_rn(__fsub_rn(__fadd_rn(areaI, ca[jj]), inter), 1e-6f);
            if (__fdiv_rn(inter, den) > 0.7f) m |= (1ull << jj);
        }
    }
    g_mask[((size_t)b * PREP + i) * NWORD + jb] = m;
}

// ---------------- 5. greedy scan: register bitmask + broadcast diagonal word ------
__global__ void __launch_bounds__(32) kScan() {
    int b = blockIdx.x, t = threadIdx.x;        // 32 threads
    const unsigned long long* mrow = g_mask + (size_t)b * PREP * NWORD;
    unsigned long long rem = 0, local = 0, useMask = 0;
    const int D = 16;
    unsigned long long bufC[D], bufD[D];
    #pragma unroll
    for (int d = 0; d < D; ++d) {
        bufC[d] = mrow[(size_t)d * NWORD + t];
        bufD[d] = mrow[(size_t)d * NWORD + (d >> 6)];
    }
    for (int i = 0; i < PRE; ++i) {
        int w = i >> 6;
        if ((i & 63) == 0) {
            local = __shfl_sync(0xFFFFFFFFu, rem, w);
            useMask = (t >= w) ? ~0ull : 0ull;   // lower words unwritten -> masked
        }
        int sl = i & (D - 1);
        unsigned long long cur = bufC[sl], dg = bufD[sl];
        int nx = i + D;
        if (nx < PRE) {
            bufC[sl] = mrow[(size_t)nx * NWORD + t];
            bufD[sl] = mrow[(size_t)nx * NWORD + (nx >> 6)];
        }
        if (!((local >> (i & 63)) & 1ull)) {     // uniform across warp
            rem |= cur & useMask;
            local |= dg;
        }
    }
    g_removed[b * NWORD + t] = rem;
}

// ---------------- 6. rank kept entries (popcount prefix), write output ----------------
__global__ void kOut(float* __restrict__ out) {
    int b = blockIdx.x, t = threadIdx.x;        // 256 threads
    __shared__ unsigned long long kw[NWORD];
    __shared__ int off[NWORD + 1];
    if (t < NWORD) {
        unsigned long long r = g_removed[b * NWORD + t];
        unsigned long long vm = (t == NWORD - 1) ? 0xFFFFull : ~0ull;  // rows < PRE
        kw[t] = (~r) & vm;
    }
    __syncthreads();
    if (t == 0) {
        int acc = 0;
        for (int wd = 0; wd < NWORD; ++wd) { off[wd] = acc; acc += __popcll(kw[wd]); }
        off[NWORD] = acc;
    }
    __syncthreads();
    int total = off[NWORD];
    float* ob = out + (size_t)b * POST * 5;
    for (int i = t; i < PRE; i += 256) {
        int wd = i >> 6, bit = i & 63;
        unsigned long long word = kw[wd];
        if ((word >> bit) & 1ull) {
            int r = off[wd] + __popcll(word & ((1ull << bit) - 1ull));
            if (r < POST) {
                float s = g_topScore[b * PREP + i];
                float4 bx = g_nmsBoxes4[b * PREP + i];
                bool fin = isfinite(s);
                ob[r * 5 + 0] = fin ? bx.x : 0.f;
                ob[r * 5 + 1] = fin ? bx.y : 0.f;
                ob[r * 5 + 2] = fin ? bx.z : 0.f;
                ob[r * 5 + 3] = fin ? bx.w : 0.f;
                ob[r * 5 + 4] = fin ? s    : 0.f;
            }
        }
    }
    for (int r = total + t; r < POST; r += 256) {
        ob[r * 5 + 0] = 0.f; ob[r * 5 + 1] = 0.f;
        ob[r * 5 + 2] = 0.f; ob[r * 5 + 3] = 0.f;
        ob[r * 5 + 4] = 0.f;
    }
}

// ---------------- launch ----------------
extern "C" void kernel_launch(void* const* d_in, const int* in_sizes, int n_in,
                              void* d_out, int out_size) {
    const float* anchors = (const float*)d_in[0];
    const float* deltas  = (const float*)d_in[1];
    const float* scores  = (const float*)d_in[2];
    float* out = (float*)d_out;
    int A = in_sizes[0] / 4;
    int B = in_sizes[2] / A;

    kInit<<<(B * NBIN + 255) / 256, 256>>>(B);
    kDecode<<<(A + 255) / 256, 256>>>(anchors, deltas, scores, A, B);
    kDecide<<<1, 32>>>(B);
    kHistFB<<<dim3(64, B), 256>>>(anchors, deltas, scores, A);
    kSelFB<<<B, 32>>>();
    kColFB<<<dim3(64, B), 256>>>(anchors, deltas, scores, A);
    kSort<<<B, 1024>>>(anchors, deltas, A);

    dim3 mg((PRE + 63) / 64, (PRE + 63) / 64, B);
    kMask<<<mg, 64>>>();
    kScan<<<B, 32>>>();
    kOut<<<B, 256>>>(out);
}